// round 14
// baseline (speedup 1.0000x reference)
#include <cuda_runtime.h>
#include <cuda_bf16.h>
#include <cstdint>

// ScaleLayer: y[b,d] = x[b,d] * exp(diag[d]);  second output = raw diag.
// x: [16384, 4096] fp32 row-major; diag: [4096] fp32.
//
// CONVERGED FINAL (reproduced 5x: total 81.95-82.08us, sigma ~0.05us;
// kernel ncu samples 74.0-76.0us @ 80.6-82.5% DRAM / 6.39-6.54 TB/s).
// Pinned at the B300 HBM/LTS streaming ceiling for 512 MiB of mandatory
// read+write traffic; the LTS chip cap is path-independent (TMA == LDG),
// so no staging scheme can exceed this. Remaining ~7.9us of total is fixed
// harness/graph overhead, invariant across all 13 tested kernel variants.
//
// Search record (13 rounds, all axes post-mortemed):
//   - MLP per thread: 4 best (8 -> regs 56, occ 44%, slower)
//   - lane layout: unit-stride best (2-adjacent interleave doubles
//     lines/LDG -> L1 wavefronts x2, -9% DRAM BW; column-fixed worse)
//   - cache hints: plain LDG/STG best (ldcs/stcs neutral-to-negative)
//   - exp: inline (4 expf/thread) fully hidden under memory stalls
//     (issue 8->14%, DRAM% unchanged); separate prologue kernel costs
//     ~2us of graph-node serialization
//   - CTA 256 vs 512: tie; loop-free exact cover beats grid-stride loops
//     by ~2us (lowest regs = 32, no branch/index overhead)
//
// Thread j handles float4s {j, j+S, j+2S, j+3S} (S = total threads); S is a
// multiple of D_DIM/4 so all four share one diag column. Diag echo: threads
// j<1024 write tail[j] (col4==j there), exact cover by blocks 0..3.

#define D_DIM 4096
#define B_DIM 16384

__global__ void __launch_bounds__(256)
scale_kernel(const float4* __restrict__ x,
             const float4* __restrict__ diag4,
             float4* __restrict__ y,
             float4* __restrict__ tail,   // d_out + B*D (raw diag echo)
             int write_tail) {
    constexpr int S = (B_DIM * D_DIM) / 4 / 4;     // 4,194,304

    const int j  = blockIdx.x * blockDim.x + threadIdx.x;
    const int j0 = j;
    const int j1 = j + S;
    const int j2 = j + 2 * S;
    const int j3 = j + 3 * S;
    const int col4 = j & (D_DIM / 4 - 1);

    // Front-batched independent loads (MLP=4) + the 16B diag load (L1-hot).
    float4 v0 = x[j0];
    float4 v1 = x[j1];
    float4 v2 = x[j2];
    float4 v3 = x[j3];
    float4 d  = diag4[col4];

    // Raw diag echo: threads j<1024 give col4 == j -> exact cover of the
    // 1024-float4 tail by blocks 0..3.
    if (write_tail && j < (D_DIM / 4)) tail[j] = d;

    // exp() inline -- MUFU work overlapped with memory stalls.
    float4 e;
    e.x = expf(d.x);
    e.y = expf(d.y);
    e.z = expf(d.z);
    e.w = expf(d.w);

    v0.x *= e.x; v0.y *= e.y; v0.z *= e.z; v0.w *= e.w;
    v1.x *= e.x; v1.y *= e.y; v1.z *= e.z; v1.w *= e.w;
    v2.x *= e.x; v2.y *= e.y; v2.z *= e.z; v2.w *= e.w;
    v3.x *= e.x; v3.y *= e.y; v3.z *= e.z; v3.w *= e.w;

    y[j0] = v0;
    y[j1] = v1;
    y[j2] = v2;
    y[j3] = v3;
}

extern "C" void kernel_launch(void* const* d_in, const int* in_sizes, int n_in,
                              void* d_out, int out_size) {
    const float* x    = (const float*)d_in[0];
    const float* diag = (const float*)d_in[1];
    float* out = (float*)d_out;

    const long long n_main = (long long)B_DIM * D_DIM;
    const int write_tail = (out_size > n_main) ? 1 : 0;

    // 16,777,216 float4 / (256 thr * 4 per thread) = 16384 CTAs, exact.
    scale_kernel<<<16384, 256>>>((const float4*)x,
                                 (const float4*)diag,
                                 (float4*)out,
                                 (float4*)(out + n_main),
                                 write_tail);
}

// round 15
// speedup vs baseline: 1.0047x; 1.0047x over previous
#include <cuda_runtime.h>
#include <cuda_bf16.h>
#include <cstdint>

// ScaleLayer: y[b,d] = x[b,d] * exp(diag[d]);  second output = raw diag.
// x: [16384, 4096] fp32 row-major; diag: [4096] fp32.
//
// CONVERGED FINAL (reproduced 6x: total 81.95-82.40us; kernel 74.0-76.0us
// @ 80.6-82.5% DRAM / 6.39-6.54 TB/s). Pinned at the B300 HBM/LTS
// streaming ceiling for 512 MiB of mandatory read+write traffic; the LTS
// chip cap is path-independent (TMA == LDG), so no staging scheme can
// exceed this. Remaining ~8us of total is fixed harness/graph overhead,
// invariant across all 14 tested kernel variants.
//
// Search record (14 rounds, all axes post-mortemed):
//   - MLP per thread: 4 best (8 -> regs 56, occ 44%, slower)
//   - lane layout: unit-stride best (2-adjacent interleave doubles
//     lines/LDG -> L1 wavefronts x2, -9% DRAM BW; column-fixed worse)
//   - cache hints: plain LDG/STG best (ldcs/stcs neutral-to-negative)
//   - exp: inline (4 expf/thread) fully hidden under memory stalls
//     (issue 8->14%, DRAM% unchanged); separate prologue kernel costs
//     ~2us of graph-node serialization
//   - CTA 256 vs 512: tie; loop-free exact cover beats grid-stride loops
//     by ~2us (lowest regs = 32, no branch/index overhead)
//
// Thread j handles float4s {j, j+S, j+2S, j+3S} (S = total threads); S is a
// multiple of D_DIM/4 so all four share one diag column. Diag echo: threads
// j<1024 write tail[j] (col4==j there), exact cover by blocks 0..3.

#define D_DIM 4096
#define B_DIM 16384

__global__ void __launch_bounds__(256)
scale_kernel(const float4* __restrict__ x,
             const float4* __restrict__ diag4,
             float4* __restrict__ y,
             float4* __restrict__ tail,   // d_out + B*D (raw diag echo)
             int write_tail) {
    constexpr int S = (B_DIM * D_DIM) / 4 / 4;     // 4,194,304

    const int j  = blockIdx.x * blockDim.x + threadIdx.x;
    const int j0 = j;
    const int j1 = j + S;
    const int j2 = j + 2 * S;
    const int j3 = j + 3 * S;
    const int col4 = j & (D_DIM / 4 - 1);

    // Front-batched independent loads (MLP=4) + the 16B diag load (L1-hot).
    float4 v0 = x[j0];
    float4 v1 = x[j1];
    float4 v2 = x[j2];
    float4 v3 = x[j3];
    float4 d  = diag4[col4];

    // Raw diag echo: threads j<1024 give col4 == j -> exact cover of the
    // 1024-float4 tail by blocks 0..3.
    if (write_tail && j < (D_DIM / 4)) tail[j] = d;

    // exp() inline -- MUFU work overlapped with memory stalls.
    float4 e;
    e.x = expf(d.x);
    e.y = expf(d.y);
    e.z = expf(d.z);
    e.w = expf(d.w);

    v0.x *= e.x; v0.y *= e.y; v0.z *= e.z; v0.w *= e.w;
    v1.x *= e.x; v1.y *= e.y; v1.z *= e.z; v1.w *= e.w;
    v2.x *= e.x; v2.y *= e.y; v2.z *= e.z; v2.w *= e.w;
    v3.x *= e.x; v3.y *= e.y; v3.z *= e.z; v3.w *= e.w;

    y[j0] = v0;
    y[j1] = v1;
    y[j2] = v2;
    y[j3] = v3;
}

extern "C" void kernel_launch(void* const* d_in, const int* in_sizes, int n_in,
                              void* d_out, int out_size) {
    const float* x    = (const float*)d_in[0];
    const float* diag = (const float*)d_in[1];
    float* out = (float*)d_out;

    const long long n_main = (long long)B_DIM * D_DIM;
    const int write_tail = (out_size > n_main) ? 1 : 0;

    // 16,777,216 float4 / (256 thr * 4 per thread) = 16384 CTAs, exact.
    scale_kernel<<<16384, 256>>>((const float4*)x,
                                 (const float4*)diag,
                                 (float4*)out,
                                 (float4*)(out + n_main),
                                 write_tail);
}